// round 8
// baseline (speedup 1.0000x reference)
#include <cuda_runtime.h>
#include <cuda_bf16.h>
#include <math.h>

// ---------------- problem constants ----------------
#define NN 50000
#define EE 800000
#define F_IN 512
#define H1 8
#define F_HID 8
#define O1 64          // H1*F_HID
#define NLAB 64
#define LRELU 0.2f

#define FULLM 0xffffffffu

// ---------------- device scratch (no allocs allowed) ----------------
__device__ ulonglong2 g_Wp[(F_IN / 2) * 32];   // W1 packed: [kpair][lane] -> {(o=2l),(o=2l+1)} f32x2
__device__ ulonglong2 g_W2p[(O1 / 2) * 32];    // W2 packed same format
__device__ float g_Wh1[(size_t)NN * O1];       // layer-1 node features
__device__ float g_es1[NN * H1];
__device__ float g_ed1[NN * H1];
__device__ float g_h1[(size_t)NN * O1];        // post-aggregation, post-ELU
__device__ float g_Wh2[(size_t)NN * NLAB];
__device__ float g_es2[NN];
__device__ float g_ed2[NN];
__device__ float g_p1[(size_t)EE * H1 + 256];  // exp(lrelu(logit)) per (sorted edge, head) (+pad, zero-init)
__device__ int   g_cnt[NN];                    // zero at entry (re-zeroed at tail of k5)
__device__ int   g_rank[EE];
__device__ int   g_off[NN + 1];
__device__ int   g_ssrc[EE + 32];              // +pad (zero-init) for unguarded batch loads

// ---------------- f32x2 helpers ----------------
__device__ __forceinline__ unsigned long long pack2(float lo, float hi) {
    unsigned long long r;
    asm("mov.b64 %0, {%1, %2};" : "=l"(r) : "f"(lo), "f"(hi));
    return r;
}
__device__ __forceinline__ void fma2(unsigned long long& acc, unsigned long long a,
                                     unsigned long long b) {
    asm("fma.rn.f32x2 %0, %1, %2, %0;" : "+l"(acc) : "l"(a), "l"(b));
}
__device__ __forceinline__ float2 unpack2(unsigned long long v) {
    float lo, hi;
    asm("mov.b64 {%0, %1}, %2;" : "=f"(lo), "=f"(hi) : "l"(v));
    return make_float2(lo, hi);
}

__device__ __forceinline__ float lrelu_f(float v) { return fmaxf(v, LRELU * v); }
__device__ __forceinline__ float elu_f(float v)   { return v > 0.f ? v : __expf(v) - 1.f; }

// ============ K1: pack W1 (32 blk) + pack W2 (4 blk) + hist (rank-storing) ============
#define HIST_BLKS ((EE + 255) / 256)
__global__ __launch_bounds__(256) void k1_prep_hist(const float* __restrict__ W1,
                                                    const float* __restrict__ W2,
                                                    const int* __restrict__ dst) {
    const int bid = blockIdx.x;
    const int tid = threadIdx.x;
    if (bid < 32) {
        int i = bid * 256 + tid;   // < 8192 = (F_IN/2)*32
        int p = i >> 5, l = i & 31;
        int o0 = 2 * l, o1 = 2 * l + 1;
        int k0 = 2 * p, k1 = 2 * p + 1;
        // W1: [H1, F_IN, F_HID]; element (k,o) at (o>>3)*4096 + k*8 + (o&7)
        float w00 = W1[(o0 >> 3) * (F_IN * F_HID) + k0 * F_HID + (o0 & 7)];
        float w10 = W1[(o0 >> 3) * (F_IN * F_HID) + k1 * F_HID + (o0 & 7)];
        float w01 = W1[(o1 >> 3) * (F_IN * F_HID) + k0 * F_HID + (o1 & 7)];
        float w11 = W1[(o1 >> 3) * (F_IN * F_HID) + k1 * F_HID + (o1 & 7)];
        ulonglong2 v;
        v.x = pack2(w00, w10);
        v.y = pack2(w01, w11);
        g_Wp[i] = v;
    } else if (bid < 36) {
        int i = (bid - 32) * 256 + tid;   // < 1024 = (O1/2)*32
        int p = i >> 5, l = i & 31;
        int o0 = 2 * l, o1 = 2 * l + 1;
        int k0 = 2 * p, k1 = 2 * p + 1;
        // W2: [1, O1, NLAB]; element (k,o) at k*64 + o
        ulonglong2 v;
        v.x = pack2(W2[k0 * NLAB + o0], W2[k1 * NLAB + o0]);
        v.y = pack2(W2[k0 * NLAB + o1], W2[k1 * NLAB + o1]);
        g_W2p[i] = v;
    } else {
        int e = (bid - 36) * 256 + tid;
        if (e < EE) g_rank[e] = atomicAdd(&g_cnt[dst[e]], 1);
    }
}

// ================= K2: gemm1 (blocks 1..) + scan (block 0) =================
#define G1_NB 64
#define G1_KC 128
__global__ __launch_bounds__(256) void k2_gemm1_scan(const float* __restrict__ x,
                                                     const float* __restrict__ a1s,
                                                     const float* __restrict__ a1d) {
    __shared__ float xs[G1_NB][G1_KC];   // 32KB (scan block reuses a corner)
    const int tid = threadIdx.x;

    if (blockIdx.x == 0) {
        // ---- exclusive scan of g_cnt -> g_off (256 threads) ----
        int* ssum = (int*)xs;
        const int CH = (NN + 255) / 256;   // 196
        int b = tid * CH;
        int e2 = b + CH; if (e2 > NN) e2 = NN;
        int s = 0;
        for (int i = b; i < e2; i++) s += g_cnt[i];
        ssum[tid] = s;
        __syncthreads();
        for (int d = 1; d < 256; d <<= 1) {
            int v = (tid >= d) ? ssum[tid - d] : 0;
            __syncthreads();
            ssum[tid] += v;
            __syncthreads();
        }
        int off = (tid == 0) ? 0 : ssum[tid - 1];
        for (int i = b; i < e2; i++) {
            g_off[i] = off;
            off += g_cnt[i];
        }
        if (tid == 255) g_off[NN] = ssum[255];
        return;
    }

    // ---- gemm1: Wh1 = x @ W1 (+ es1/ed1 epilogue), f32x2 ----
    const int lane = tid & 31;
    const int w = tid >> 5;
    const int nb0 = (blockIdx.x - 1) * G1_NB;

    unsigned long long acc[8][2];
#pragma unroll
    for (int n = 0; n < 8; n++) { acc[n][0] = 0ull; acc[n][1] = 0ull; }

    for (int kt = 0; kt < F_IN; kt += G1_KC) {
        __syncthreads();
        for (int idx = tid; idx < G1_NB * (G1_KC / 4); idx += 256) {
            int n = idx >> 5;
            int c = idx & 31;
            int g = nb0 + n;
            float4 v = make_float4(0.f, 0.f, 0.f, 0.f);
            if (g < NN) v = *(const float4*)&x[(size_t)g * F_IN + kt + c * 4];
            *(float4*)&xs[n][c * 4] = v;
        }
        __syncthreads();

        const int nrow = w * 8;
        const int pbase = kt >> 1;
#pragma unroll 4
        for (int q = 0; q < G1_KC / 2; q += 2) {
            ulonglong2 wA = g_Wp[(pbase + q) * 32 + lane];
            ulonglong2 wB = g_Wp[(pbase + q + 1) * 32 + lane];
#pragma unroll
            for (int n = 0; n < 8; n++) {
                ulonglong2 xv = *(const ulonglong2*)&xs[nrow + n][2 * q];
                fma2(acc[n][0], xv.x, wA.x);
                fma2(acc[n][1], xv.x, wA.y);
                fma2(acc[n][0], xv.y, wB.x);
                fma2(acc[n][1], xv.y, wB.y);
            }
        }
    }

    const float as0 = a1s[2 * lane], as1 = a1s[2 * lane + 1];
    const float ad0 = a1d[2 * lane], ad1 = a1d[2 * lane + 1];
#pragma unroll
    for (int n = 0; n < 8; n++) {
        int g = nb0 + w * 8 + n;
        if (g >= NN) continue;  // uniform across warp
        float2 p0 = unpack2(acc[n][0]);
        float2 p1 = unpack2(acc[n][1]);
        float o0 = p0.x + p0.y;
        float o1 = p1.x + p1.y;
        *(float2*)&g_Wh1[(size_t)g * O1 + 2 * lane] = make_float2(o0, o1);
        float ps = o0 * as0 + o1 * as1;
        float pd = o0 * ad0 + o1 * ad1;
        ps += __shfl_xor_sync(FULLM, ps, 1);
        ps += __shfl_xor_sync(FULLM, ps, 2);
        pd += __shfl_xor_sync(FULLM, pd, 1);
        pd += __shfl_xor_sync(FULLM, pd, 2);
        if ((lane & 3) == 0) {
            g_es1[g * H1 + (lane >> 2)] = ps;
            g_ed1[g * H1 + (lane >> 2)] = pd;
        }
    }
}

// ====== K3: scatter (atomic-free) + edge-parallel p1 = exp(lrelu(es+ed)) ======
__global__ void k3_scatter_p1(const int* __restrict__ src, const int* __restrict__ dst) {
    int e = blockIdx.x * blockDim.x + threadIdx.x;
    if (e >= EE) return;
    int d = dst[e];
    int s = src[e];
    int pos = g_off[d] + g_rank[e];
    g_ssrc[pos] = s;
    float4 esa = *(const float4*)&g_es1[s * H1];
    float4 esb = *(const float4*)&g_es1[s * H1 + 4];
    float4 eda = *(const float4*)&g_ed1[d * H1];
    float4 edb = *(const float4*)&g_ed1[d * H1 + 4];
    float4 pa, pb;
    pa.x = __expf(lrelu_f(esa.x + eda.x));
    pa.y = __expf(lrelu_f(esa.y + eda.y));
    pa.z = __expf(lrelu_f(esa.z + eda.z));
    pa.w = __expf(lrelu_f(esa.w + eda.w));
    pb.x = __expf(lrelu_f(esb.x + edb.x));
    pb.y = __expf(lrelu_f(esb.y + edb.y));
    pb.z = __expf(lrelu_f(esb.z + edb.z));
    pb.w = __expf(lrelu_f(esb.w + edb.w));
    *(float4*)&g_p1[(size_t)pos * H1] = pa;
    *(float4*)&g_p1[(size_t)pos * H1 + 4] = pb;
}

// ====== K4: layer-1 aggregate, batch-8 unrolled (MLP=8, low waste) + ELU ======
__global__ __launch_bounds__(256) void k4_agg1() {
    int node = (blockIdx.x * blockDim.x + threadIdx.x) >> 5;
    int lane = threadIdx.x & 31;
    if (node >= NN) return;
    const int beg = g_off[node], end = g_off[node + 1];
    const int srcg = lane & 0x1C;   // (h<<2): shfl source group base
    const int e4 = lane & 3;        // edge sub-index within head group
    const int e8 = lane & 7;        // edge index for src staging
    const int h = lane >> 2;

    float sumP = 0.f;
    unsigned long long acc0 = 0ull, acc1 = 0ull;
    for (int base = beg; base < end; base += 8) {
        const int m = end - base;
        // lanes 0-7 stage the 8 src ids (pad zero-init -> safe, s=0 valid row)
        int s_l = g_ssrc[base + e8];
        // lane (h, e4) stages p for edges e4 and 4+e4 of head h; zero if past end
        float tA = g_p1[(size_t)(base + e4) * H1 + h];
        float tB = g_p1[(size_t)(base + 4 + e4) * H1 + h];
        float pA = (e4 < m) ? tA : 0.f;
        float pB = (4 + e4 < m) ? tB : 0.f;
        sumP += pA + pB;
#pragma unroll
        for (int j = 0; j < 8; j++) {
            int s   = __shfl_sync(FULLM, s_l, j);
            float p = __shfl_sync(FULLM, (j < 4) ? pA : pB, srcg | (j & 3));
            unsigned long long w2 = *(const unsigned long long*)
                &g_Wh1[(size_t)s * O1 + 2 * lane];
            if (j & 1) fma2(acc1, pack2(p, p), w2);
            else       fma2(acc0, pack2(p, p), w2);
        }
    }
    // per-head sum: 4 lanes of group h jointly cover all edges
    sumP += __shfl_xor_sync(FULLM, sumP, 1);
    sumP += __shfl_xor_sync(FULLM, sumP, 2);

    const float inv = 1.f / (sumP + 1e-10f);
    float2 a0 = unpack2(acc0);
    float2 a1 = unpack2(acc1);
    *(float2*)&g_h1[(size_t)node * O1 + 2 * lane] =
        make_float2(elu_f((a0.x + a1.x) * inv), elu_f((a0.y + a1.y) * inv));
}

// ========= K4c: GEMM2 (batched, W2 packed, f32x2) + es2/ed2 epilogue =========
#define G2_NB 64
__global__ __launch_bounds__(256) void k4c_gemm2(const float* __restrict__ a2s,
                                                 const float* __restrict__ a2d) {
    __shared__ float hs[G2_NB][O1];   // 16KB
    const int tid = threadIdx.x;
    const int lane = tid & 31;
    const int w = tid >> 5;
    const int nb0 = blockIdx.x * G2_NB;

    for (int idx = tid; idx < G2_NB * (O1 / 4); idx += 256) {
        int n = idx >> 4;
        int c = idx & 15;
        int g = nb0 + n;
        float4 v = make_float4(0.f, 0.f, 0.f, 0.f);
        if (g < NN) v = *(const float4*)&g_h1[(size_t)g * O1 + c * 4];
        *(float4*)&hs[n][c * 4] = v;
    }
    __syncthreads();

    unsigned long long acc[8][2];
#pragma unroll
    for (int n = 0; n < 8; n++) { acc[n][0] = 0ull; acc[n][1] = 0ull; }

    const int nrow = w * 8;
#pragma unroll 4
    for (int q = 0; q < O1 / 2; q += 2) {
        ulonglong2 wA = g_W2p[q * 32 + lane];
        ulonglong2 wB = g_W2p[(q + 1) * 32 + lane];
#pragma unroll
        for (int n = 0; n < 8; n++) {
            ulonglong2 xv = *(const ulonglong2*)&hs[nrow + n][2 * q];
            fma2(acc[n][0], xv.x, wA.x);
            fma2(acc[n][1], xv.x, wA.y);
            fma2(acc[n][0], xv.y, wB.x);
            fma2(acc[n][1], xv.y, wB.y);
        }
    }

    const float as0 = a2s[2 * lane], as1 = a2s[2 * lane + 1];
    const float ad0 = a2d[2 * lane], ad1 = a2d[2 * lane + 1];
#pragma unroll
    for (int n = 0; n < 8; n++) {
        int g = nb0 + w * 8 + n;
        if (g >= NN) continue;  // uniform across warp
        float2 p0 = unpack2(acc[n][0]);
        float2 p1 = unpack2(acc[n][1]);
        float o0 = p0.x + p0.y;
        float o1 = p1.x + p1.y;
        *(float2*)&g_Wh2[(size_t)g * NLAB + 2 * lane] = make_float2(o0, o1);
        float ps = o0 * as0 + o1 * as1;
        float pd = o0 * ad0 + o1 * ad1;
#pragma unroll
        for (int o = 16; o; o >>= 1) {
            ps += __shfl_xor_sync(FULLM, ps, o);
            pd += __shfl_xor_sync(FULLM, pd, o);
        }
        if (lane == 0) { g_es2[g] = ps; g_ed2[g] = pd; }
    }
}

// ====== K5: layer-2 aggregate, batch-8 + sw-pipelined gather + softmax ======
__global__ __launch_bounds__(256) void k5_agg2(float* __restrict__ out) {
    int gid = blockIdx.x * blockDim.x + threadIdx.x;
    if (gid < NN) g_cnt[gid] = 0;   // leave cnt zeroed for the next call

    int node = gid >> 5;
    int lane = threadIdx.x & 31;
    if (node >= NN) return;
    const int beg = g_off[node], end = g_off[node + 1];
    const float ed = g_ed2[node];
    const int e8 = lane & 7;

    float sumP = 0.f;
    unsigned long long acc0 = 0ull, acc1 = 0ull;

    // depth-2 pipeline on the ssrc -> es2 gather chain (pads make loads safe)
    int   s_l = g_ssrc[beg + e8];
    float v_l = g_es2[s_l];
    for (int base = beg; base < end; base += 8) {
        int   s_n = g_ssrc[base + 8 + e8];
        float v_n = g_es2[s_n];

        const int m = end - base;
        float p_l = (e8 < m) ? __expf(lrelu_f(v_l + ed)) : 0.f;
        if (lane < 8) sumP += p_l;   // lanes 8-31 hold duplicates
#pragma unroll
        for (int j = 0; j < 8; j++) {
            int s   = __shfl_sync(FULLM, s_l, j);
            float p = __shfl_sync(FULLM, p_l, j);
            unsigned long long w2 = *(const unsigned long long*)
                &g_Wh2[(size_t)s * NLAB + 2 * lane];
            if (j & 1) fma2(acc1, pack2(p, p), w2);
            else       fma2(acc0, pack2(p, p), w2);
        }
        s_l = s_n; v_l = v_n;
    }
#pragma unroll
    for (int o = 16; o; o >>= 1) sumP += __shfl_xor_sync(FULLM, sumP, o);

    const float inv = 1.f / (sumP + 1e-10f);
    float2 a0 = unpack2(acc0);
    float2 a1 = unpack2(acc1);
    float o0 = (a0.x + a1.x) * inv;
    float o1 = (a0.y + a1.y) * inv;

    // head-mean is identity (H2=1); fused softmax over 64 classes
    float m2 = fmaxf(o0, o1);
#pragma unroll
    for (int o = 16; o; o >>= 1) m2 = fmaxf(m2, __shfl_xor_sync(FULLM, m2, o));
    float e0 = __expf(o0 - m2);
    float e1 = __expf(o1 - m2);
    float s2 = e0 + e1;
#pragma unroll
    for (int o = 16; o; o >>= 1) s2 += __shfl_xor_sync(FULLM, s2, o);
    float r = 1.f / s2;
    *(float2*)&out[(size_t)node * NLAB + 2 * lane] = make_float2(e0 * r, e1 * r);
}

// ---------------- launch ----------------
extern "C" void kernel_launch(void* const* d_in, const int* in_sizes, int n_in,
                              void* d_out, int out_size) {
    const float* x    = (const float*)d_in[0];
    const float* W1   = (const float*)d_in[1];
    const float* a1s  = (const float*)d_in[2];
    const float* a1d  = (const float*)d_in[3];
    const float* W2   = (const float*)d_in[4];
    const float* a2s  = (const float*)d_in[5];
    const float* a2d  = (const float*)d_in[6];
    const int*   src  = (const int*)d_in[7];
    const int*   dst  = (const int*)d_in[8];
    float* out = (float*)d_out;

    k1_prep_hist<<<36 + HIST_BLKS, 256>>>(W1, W2, dst);
    k2_gemm1_scan<<<1 + (NN + G1_NB - 1) / G1_NB, 256>>>(x, a1s, a1d);
    k3_scatter_p1<<<HIST_BLKS, 256>>>(src, dst);
    k4_agg1<<<(NN * 32 + 255) / 256, 256>>>();
    k4c_gemm2<<<(NN + G2_NB - 1) / G2_NB, 256>>>(a2s, a2d);
    k5_agg2<<<(NN * 32 + 255) / 256, 256>>>(out);
}

// round 9
// speedup vs baseline: 1.0669x; 1.0669x over previous
#include <cuda_runtime.h>
#include <cuda_bf16.h>
#include <math.h>

// ---------------- problem constants ----------------
#define NN 50000
#define EE 800000
#define F_IN 512
#define H1 8
#define F_HID 8
#define O1 64          // H1*F_HID
#define NLAB 64
#define LRELU 0.2f

#define FULLM 0xffffffffu

// ---------------- device scratch (no allocs allowed) ----------------
__device__ ulonglong2 g_Wp[(F_IN / 2) * 32];   // W1 packed: [kpair][lane] -> {(o=2l),(o=2l+1)} f32x2
__device__ ulonglong2 g_W2p[(O1 / 2) * 32];    // W2 packed same format
__device__ float g_Wh1[(size_t)NN * O1];       // layer-1 node features
__device__ float g_es1[NN * H1];
__device__ float g_ed1[NN * H1];
__device__ float g_h1[(size_t)NN * O1];        // post-aggregation, post-ELU
__device__ float g_Wh2[(size_t)NN * NLAB];
__device__ float g_es2[NN];
__device__ float g_ed2[NN];
__device__ int   g_cnt[NN];                    // zero at entry (re-zeroed at tail of k5)
__device__ int   g_rank[EE];
__device__ int   g_off[NN + 1];
__device__ int   g_ssrc[EE + 32];              // +pad (zero-init) for unguarded pipelined loads

// ---------------- f32x2 helpers ----------------
__device__ __forceinline__ unsigned long long pack2(float lo, float hi) {
    unsigned long long r;
    asm("mov.b64 %0, {%1, %2};" : "=l"(r) : "f"(lo), "f"(hi));
    return r;
}
__device__ __forceinline__ void fma2(unsigned long long& acc, unsigned long long a,
                                     unsigned long long b) {
    asm("fma.rn.f32x2 %0, %1, %2, %0;" : "+l"(acc) : "l"(a), "l"(b));
}
__device__ __forceinline__ float2 unpack2(unsigned long long v) {
    float lo, hi;
    asm("mov.b64 {%0, %1}, %2;" : "=f"(lo), "=f"(hi) : "l"(v));
    return make_float2(lo, hi);
}

__device__ __forceinline__ float lrelu_f(float v) { return fmaxf(v, LRELU * v); }
__device__ __forceinline__ float elu_f(float v)   { return v > 0.f ? v : __expf(v) - 1.f; }

// ============ K1: pack W1 (32 blk) + pack W2 (4 blk) + hist (rank-storing) ============
#define HIST_BLKS ((EE + 255) / 256)
__global__ __launch_bounds__(256) void k1_prep_hist(const float* __restrict__ W1,
                                                    const float* __restrict__ W2,
                                                    const int* __restrict__ dst) {
    const int bid = blockIdx.x;
    const int tid = threadIdx.x;
    if (bid < 32) {
        int i = bid * 256 + tid;   // < 8192 = (F_IN/2)*32
        int p = i >> 5, l = i & 31;
        int o0 = 2 * l, o1 = 2 * l + 1;
        int k0 = 2 * p, k1 = 2 * p + 1;
        // W1: [H1, F_IN, F_HID]; element (k,o) at (o>>3)*4096 + k*8 + (o&7)
        float w00 = W1[(o0 >> 3) * (F_IN * F_HID) + k0 * F_HID + (o0 & 7)];
        float w10 = W1[(o0 >> 3) * (F_IN * F_HID) + k1 * F_HID + (o0 & 7)];
        float w01 = W1[(o1 >> 3) * (F_IN * F_HID) + k0 * F_HID + (o1 & 7)];
        float w11 = W1[(o1 >> 3) * (F_IN * F_HID) + k1 * F_HID + (o1 & 7)];
        ulonglong2 v;
        v.x = pack2(w00, w10);
        v.y = pack2(w01, w11);
        g_Wp[i] = v;
    } else if (bid < 36) {
        int i = (bid - 32) * 256 + tid;   // < 1024 = (O1/2)*32
        int p = i >> 5, l = i & 31;
        int o0 = 2 * l, o1 = 2 * l + 1;
        int k0 = 2 * p, k1 = 2 * p + 1;
        // W2: [1, O1, NLAB]; element (k,o) at k*64 + o
        ulonglong2 v;
        v.x = pack2(W2[k0 * NLAB + o0], W2[k1 * NLAB + o0]);
        v.y = pack2(W2[k0 * NLAB + o1], W2[k1 * NLAB + o1]);
        g_W2p[i] = v;
    } else {
        int e = (bid - 36) * 256 + tid;
        if (e < EE) g_rank[e] = atomicAdd(&g_cnt[dst[e]], 1);
    }
}

// ================= K2: gemm1 (blocks 1..) + scan (block 0) =================
#define G1_NB 64
#define G1_KC 128
__global__ __launch_bounds__(256) void k2_gemm1_scan(const float* __restrict__ x,
                                                     const float* __restrict__ a1s,
                                                     const float* __restrict__ a1d) {
    __shared__ float xs[G1_NB][G1_KC];   // 32KB (scan block reuses a corner)
    const int tid = threadIdx.x;

    if (blockIdx.x == 0) {
        // ---- exclusive scan of g_cnt -> g_off (256 threads) ----
        int* ssum = (int*)xs;
        const int CH = (NN + 255) / 256;   // 196
        int b = tid * CH;
        int e2 = b + CH; if (e2 > NN) e2 = NN;
        int s = 0;
        for (int i = b; i < e2; i++) s += g_cnt[i];
        ssum[tid] = s;
        __syncthreads();
        for (int d = 1; d < 256; d <<= 1) {
            int v = (tid >= d) ? ssum[tid - d] : 0;
            __syncthreads();
            ssum[tid] += v;
            __syncthreads();
        }
        int off = (tid == 0) ? 0 : ssum[tid - 1];
        for (int i = b; i < e2; i++) {
            g_off[i] = off;
            off += g_cnt[i];
        }
        if (tid == 255) g_off[NN] = ssum[255];
        return;
    }

    // ---- gemm1: Wh1 = x @ W1 (+ es1/ed1 epilogue), f32x2 ----
    const int lane = tid & 31;
    const int w = tid >> 5;
    const int nb0 = (blockIdx.x - 1) * G1_NB;

    unsigned long long acc[8][2];
#pragma unroll
    for (int n = 0; n < 8; n++) { acc[n][0] = 0ull; acc[n][1] = 0ull; }

    for (int kt = 0; kt < F_IN; kt += G1_KC) {
        __syncthreads();
        for (int idx = tid; idx < G1_NB * (G1_KC / 4); idx += 256) {
            int n = idx >> 5;
            int c = idx & 31;
            int g = nb0 + n;
            float4 v = make_float4(0.f, 0.f, 0.f, 0.f);
            if (g < NN) v = *(const float4*)&x[(size_t)g * F_IN + kt + c * 4];
            *(float4*)&xs[n][c * 4] = v;
        }
        __syncthreads();

        const int nrow = w * 8;
        const int pbase = kt >> 1;
#pragma unroll 4
        for (int q = 0; q < G1_KC / 2; q += 2) {
            ulonglong2 wA = g_Wp[(pbase + q) * 32 + lane];
            ulonglong2 wB = g_Wp[(pbase + q + 1) * 32 + lane];
#pragma unroll
            for (int n = 0; n < 8; n++) {
                ulonglong2 xv = *(const ulonglong2*)&xs[nrow + n][2 * q];
                fma2(acc[n][0], xv.x, wA.x);
                fma2(acc[n][1], xv.x, wA.y);
                fma2(acc[n][0], xv.y, wB.x);
                fma2(acc[n][1], xv.y, wB.y);
            }
        }
    }

    const float as0 = a1s[2 * lane], as1 = a1s[2 * lane + 1];
    const float ad0 = a1d[2 * lane], ad1 = a1d[2 * lane + 1];
#pragma unroll
    for (int n = 0; n < 8; n++) {
        int g = nb0 + w * 8 + n;
        if (g >= NN) continue;  // uniform across warp
        float2 p0 = unpack2(acc[n][0]);
        float2 p1 = unpack2(acc[n][1]);
        float o0 = p0.x + p0.y;
        float o1 = p1.x + p1.y;
        *(float2*)&g_Wh1[(size_t)g * O1 + 2 * lane] = make_float2(o0, o1);
        float ps = o0 * as0 + o1 * as1;
        float pd = o0 * ad0 + o1 * ad1;
        ps += __shfl_xor_sync(FULLM, ps, 1);
        ps += __shfl_xor_sync(FULLM, ps, 2);
        pd += __shfl_xor_sync(FULLM, pd, 1);
        pd += __shfl_xor_sync(FULLM, pd, 2);
        if ((lane & 3) == 0) {
            g_es1[g * H1 + (lane >> 2)] = ps;
            g_ed1[g * H1 + (lane >> 2)] = pd;
        }
    }
}

// ================= K3: pure scatter (atomic-free, rank-based) =================
__global__ void k3_scatter(const int* __restrict__ src, const int* __restrict__ dst) {
    int e = blockIdx.x * blockDim.x + threadIdx.x;
    if (e < EE) g_ssrc[g_off[dst[e]] + g_rank[e]] = src[e];
}

// ====== K4: layer-1 aggregate, batch-8, inline p (pipelined es1 gather) + ELU ======
__global__ __launch_bounds__(256) void k4_agg1() {
    int node = (blockIdx.x * blockDim.x + threadIdx.x) >> 5;
    int lane = threadIdx.x & 31;
    if (node >= NN) return;
    const int beg = g_off[node], end = g_off[node + 1];
    const int srcg = lane & 0x1C;   // (h<<2): shfl source group base
    const int e4 = lane & 3;        // edge sub-index within head group
    const int e8 = lane & 7;        // edge index for src staging
    const int h = lane >> 2;
    const float edh = g_ed1[node * H1 + h];

    // prefetch batch 0 (pads zero-init -> s=0 row reads are safe)
    int   s_l = g_ssrc[beg + e8];
    int   sA  = __shfl_sync(FULLM, s_l, e4);
    int   sB  = __shfl_sync(FULLM, s_l, 4 + e4);
    float esA = g_es1[sA * H1 + h];
    float esB = g_es1[sB * H1 + h];

    float sumP = 0.f;
    unsigned long long acc0 = 0ull, acc1 = 0ull;
    for (int base = beg; base < end; base += 8) {
        // prefetch next batch's src + es gathers (overlaps with this batch's FMAs)
        int   s_n  = g_ssrc[base + 8 + e8];
        int   sAn  = __shfl_sync(FULLM, s_n, e4);
        int   sBn  = __shfl_sync(FULLM, s_n, 4 + e4);
        float esAn = g_es1[sAn * H1 + h];
        float esBn = g_es1[sBn * H1 + h];

        const int m = end - base;
        // lane (h, e4) owns p for edges e4 and 4+e4 of head h
        float pA = (e4 < m)     ? __expf(lrelu_f(esA + edh)) : 0.f;
        float pB = (4 + e4 < m) ? __expf(lrelu_f(esB + edh)) : 0.f;
        sumP += pA + pB;
#pragma unroll
        for (int j = 0; j < 8; j++) {
            int s   = __shfl_sync(FULLM, s_l, j);
            float p = __shfl_sync(FULLM, (j < 4) ? pA : pB, srcg | (j & 3));
            unsigned long long w2 = *(const unsigned long long*)
                &g_Wh1[(size_t)s * O1 + 2 * lane];
            if (j & 1) fma2(acc1, pack2(p, p), w2);
            else       fma2(acc0, pack2(p, p), w2);
        }
        s_l = s_n; esA = esAn; esB = esBn;
    }
    // per-head sum: 4 lanes of group h jointly cover all edges
    sumP += __shfl_xor_sync(FULLM, sumP, 1);
    sumP += __shfl_xor_sync(FULLM, sumP, 2);

    const float inv = 1.f / (sumP + 1e-10f);
    float2 a0 = unpack2(acc0);
    float2 a1 = unpack2(acc1);
    *(float2*)&g_h1[(size_t)node * O1 + 2 * lane] =
        make_float2(elu_f((a0.x + a1.x) * inv), elu_f((a0.y + a1.y) * inv));
}

// ========= K4c: GEMM2 (batched, W2 packed, f32x2) + es2/ed2 epilogue =========
#define G2_NB 64
__global__ __launch_bounds__(256) void k4c_gemm2(const float* __restrict__ a2s,
                                                 const float* __restrict__ a2d) {
    __shared__ float hs[G2_NB][O1];   // 16KB
    const int tid = threadIdx.x;
    const int lane = tid & 31;
    const int w = tid >> 5;
    const int nb0 = blockIdx.x * G2_NB;

    for (int idx = tid; idx < G2_NB * (O1 / 4); idx += 256) {
        int n = idx >> 4;
        int c = idx & 15;
        int g = nb0 + n;
        float4 v = make_float4(0.f, 0.f, 0.f, 0.f);
        if (g < NN) v = *(const float4*)&g_h1[(size_t)g * O1 + c * 4];
        *(float4*)&hs[n][c * 4] = v;
    }
    __syncthreads();

    unsigned long long acc[8][2];
#pragma unroll
    for (int n = 0; n < 8; n++) { acc[n][0] = 0ull; acc[n][1] = 0ull; }

    const int nrow = w * 8;
#pragma unroll 4
    for (int q = 0; q < O1 / 2; q += 2) {
        ulonglong2 wA = g_W2p[q * 32 + lane];
        ulonglong2 wB = g_W2p[(q + 1) * 32 + lane];
#pragma unroll
        for (int n = 0; n < 8; n++) {
            ulonglong2 xv = *(const ulonglong2*)&hs[nrow + n][2 * q];
            fma2(acc[n][0], xv.x, wA.x);
            fma2(acc[n][1], xv.x, wA.y);
            fma2(acc[n][0], xv.y, wB.x);
            fma2(acc[n][1], xv.y, wB.y);
        }
    }

    const float as0 = a2s[2 * lane], as1 = a2s[2 * lane + 1];
    const float ad0 = a2d[2 * lane], ad1 = a2d[2 * lane + 1];
#pragma unroll
    for (int n = 0; n < 8; n++) {
        int g = nb0 + w * 8 + n;
        if (g >= NN) continue;  // uniform across warp
        float2 p0 = unpack2(acc[n][0]);
        float2 p1 = unpack2(acc[n][1]);
        float o0 = p0.x + p0.y;
        float o1 = p1.x + p1.y;
        *(float2*)&g_Wh2[(size_t)g * NLAB + 2 * lane] = make_float2(o0, o1);
        float ps = o0 * as0 + o1 * as1;
        float pd = o0 * ad0 + o1 * ad1;
#pragma unroll
        for (int o = 16; o; o >>= 1) {
            ps += __shfl_xor_sync(FULLM, ps, o);
            pd += __shfl_xor_sync(FULLM, pd, o);
        }
        if (lane == 0) { g_es2[g] = ps; g_ed2[g] = pd; }
    }
}

// ====== K5: layer-2 aggregate, batch-8 + sw-pipelined gather + softmax ======
__global__ __launch_bounds__(256) void k5_agg2(float* __restrict__ out) {
    int gid = blockIdx.x * blockDim.x + threadIdx.x;
    if (gid < NN) g_cnt[gid] = 0;   // leave cnt zeroed for the next call

    int node = gid >> 5;
    int lane = threadIdx.x & 31;
    if (node >= NN) return;
    const int beg = g_off[node], end = g_off[node + 1];
    const float ed = g_ed2[node];
    const int e8 = lane & 7;

    float sumP = 0.f;
    unsigned long long acc0 = 0ull, acc1 = 0ull;

    // depth-2 pipeline on the ssrc -> es2 gather chain (pads make loads safe)
    int   s_l = g_ssrc[beg + e8];
    float v_l = g_es2[s_l];
    for (int base = beg; base < end; base += 8) {
        int   s_n = g_ssrc[base + 8 + e8];
        float v_n = g_es2[s_n];

        const int m = end - base;
        float p_l = (e8 < m) ? __expf(lrelu_f(v_l + ed)) : 0.f;
        if (lane < 8) sumP += p_l;   // lanes 8-31 hold duplicates
#pragma unroll
        for (int j = 0; j < 8; j++) {
            int s   = __shfl_sync(FULLM, s_l, j);
            float p = __shfl_sync(FULLM, p_l, j);
            unsigned long long w2 = *(const unsigned long long*)
                &g_Wh2[(size_t)s * NLAB + 2 * lane];
            if (j & 1) fma2(acc1, pack2(p, p), w2);
            else       fma2(acc0, pack2(p, p), w2);
        }
        s_l = s_n; v_l = v_n;
    }
#pragma unroll
    for (int o = 16; o; o >>= 1) sumP += __shfl_xor_sync(FULLM, sumP, o);

    const float inv = 1.f / (sumP + 1e-10f);
    float2 a0 = unpack2(acc0);
    float2 a1 = unpack2(acc1);
    float o0 = (a0.x + a1.x) * inv;
    float o1 = (a0.y + a1.y) * inv;

    // head-mean is identity (H2=1); fused softmax over 64 classes
    float m2 = fmaxf(o0, o1);
#pragma unroll
    for (int o = 16; o; o >>= 1) m2 = fmaxf(m2, __shfl_xor_sync(FULLM, m2, o));
    float e0 = __expf(o0 - m2);
    float e1 = __expf(o1 - m2);
    float s2 = e0 + e1;
#pragma unroll
    for (int o = 16; o; o >>= 1) s2 += __shfl_xor_sync(FULLM, s2, o);
    float r = 1.f / s2;
    *(float2*)&out[(size_t)node * NLAB + 2 * lane] = make_float2(e0 * r, e1 * r);
}

// ---------------- launch ----------------
extern "C" void kernel_launch(void* const* d_in, const int* in_sizes, int n_in,
                              void* d_out, int out_size) {
    const float* x    = (const float*)d_in[0];
    const float* W1   = (const float*)d_in[1];
    const float* a1s  = (const float*)d_in[2];
    const float* a1d  = (const float*)d_in[3];
    const float* W2   = (const float*)d_in[4];
    const float* a2s  = (const float*)d_in[5];
    const float* a2d  = (const float*)d_in[6];
    const int*   src  = (const int*)d_in[7];
    const int*   dst  = (const int*)d_in[8];
    float* out = (float*)d_out;

    k1_prep_hist<<<36 + HIST_BLKS, 256>>>(W1, W2, dst);
    k2_gemm1_scan<<<1 + (NN + G1_NB - 1) / G1_NB, 256>>>(x, a1s, a1d);
    k3_scatter<<<HIST_BLKS, 256>>>(src, dst);
    k4_agg1<<<(NN * 32 + 255) / 256, 256>>>();
    k4c_gemm2<<<(NN + G2_NB - 1) / G2_NB, 256>>>(a2s, a2d);
    k5_agg2<<<(NN * 32 + 255) / 256, 256>>>(out);
}